// round 1
// baseline (speedup 1.0000x reference)
#include <cuda_runtime.h>

// Perona-Malik nonlinear diffusion, 3 iterations, fused per-iteration stencil.
// image: (16, 1, 1024, 1024) fp32. Each iteration:
//   gx,gy = Sobel/8 (zero-padded SAME)
//   c     = k^2 / (k^2 + gx^2 + gy^2 + eps)   [sqrt cancels algebraically]
//   flux  = c * (gx, gy)
//   div   = Sobel_x(flux_x) + Sobel_y(flux_y) (zero-padded SAME on flux)
//   out   = in + DT * div
// Fused: one kernel per iteration, 5x5 effective stencil via smem staging.

#define NB 16
#define H  1024
#define W  1024

#define TX 32
#define TY 32

#define KAPPA2 0.0025f
#define DT     0.25f
#define EPS    1e-8f

// scratch for ping-pong between iterations (no cudaMalloc allowed)
__device__ float g_scratch[(size_t)NB * H * W];

__global__ __launch_bounds__(256)
void pm_iter_kernel(const float* __restrict__ in, float* __restrict__ out)
{
    // smem: input halo (36x36), flux (34x34 x2)
    __shared__ float s_in[TY + 4][TX + 4];
    __shared__ float s_fx[TY + 2][TX + 2];
    __shared__ float s_fy[TY + 2][TX + 2];

    const int tx  = threadIdx.x;           // 0..31
    const int ty  = threadIdx.y;           // 0..7
    const int tid = ty * 32 + tx;          // 0..255

    const int bx = blockIdx.x * TX;
    const int by = blockIdx.y * TY;
    const size_t plane = (size_t)blockIdx.z * (size_t)(H * W);
    const float* __restrict__ img  = in  + plane;
    float*       __restrict__ outp = out + plane;

    // ---- stage 0: load 36x36 input halo (zero-padded at image border) ----
    #pragma unroll
    for (int i = tid; i < (TY + 4) * (TX + 4); i += 256) {
        const int r = i / (TX + 4);
        const int c = i % (TX + 4);
        const int gy = by + r - 2;
        const int gx = bx + c - 2;
        float v = 0.0f;
        if (gy >= 0 && gy < H && gx >= 0 && gx < W)
            v = img[(size_t)gy * W + gx];
        s_in[r][c] = v;
    }
    __syncthreads();

    // ---- stage 1: flux on 34x34 (tile + 1 halo ring) ----
    #pragma unroll
    for (int i = tid; i < (TY + 2) * (TX + 2); i += 256) {
        const int r = i / (TX + 2);
        const int c = i % (TX + 2);
        const int gy = by + r - 1;
        const int gx = bx + c - 1;
        float fx = 0.0f, fy = 0.0f;
        if (gy >= 0 && gy < H && gx >= 0 && gx < W) {
            const int rr = r + 1, cc = c + 1;   // center in s_in coords
            const float p00 = s_in[rr - 1][cc - 1];
            const float p01 = s_in[rr - 1][cc    ];
            const float p02 = s_in[rr - 1][cc + 1];
            const float p10 = s_in[rr    ][cc - 1];
            const float p12 = s_in[rr    ][cc + 1];
            const float p20 = s_in[rr + 1][cc - 1];
            const float p21 = s_in[rr + 1][cc    ];
            const float p22 = s_in[rr + 1][cc + 1];
            const float gxv = ((p02 - p00) + 2.0f * (p12 - p10) + (p22 - p20)) * 0.125f;
            const float gyv = ((p20 - p00) + 2.0f * (p21 - p01) + (p22 - p02)) * 0.125f;
            const float s   = fmaf(gxv, gxv, fmaf(gyv, gyv, EPS));
            const float cf  = __fdividef(KAPPA2, KAPPA2 + s);
            fx = cf * gxv;
            fy = cf * gyv;
        }
        s_fx[r][c] = fx;
        s_fy[r][c] = fy;
    }
    __syncthreads();

    // ---- stage 2: divergence + update on 32x32 tile ----
    #pragma unroll
    for (int yy = ty; yy < TY; yy += 8) {
        const int r = yy + 1;     // flux coords center
        const int c = tx + 1;
        const float divx = ((s_fx[r - 1][c + 1] - s_fx[r - 1][c - 1])
                   + 2.0f * (s_fx[r    ][c + 1] - s_fx[r    ][c - 1])
                   +        (s_fx[r + 1][c + 1] - s_fx[r + 1][c - 1])) * 0.125f;
        const float divy = ((s_fy[r + 1][c - 1] - s_fy[r - 1][c - 1])
                   + 2.0f * (s_fy[r + 1][c    ] - s_fy[r - 1][c    ])
                   +        (s_fy[r + 1][c + 1] - s_fy[r - 1][c + 1])) * 0.125f;
        const float res = fmaf(DT, divx + divy, s_in[yy + 2][tx + 2]);
        outp[(size_t)(by + yy) * W + (bx + tx)] = res;
    }
}

extern "C" void kernel_launch(void* const* d_in, const int* in_sizes, int n_in,
                              void* d_out, int out_size)
{
    const float* image = (const float*)d_in[0];
    float* out = (float*)d_out;

    dim3 block(32, 8, 1);
    dim3 grid(W / TX, H / TY, NB);

    // iter 1: image -> d_out
    pm_iter_kernel<<<grid, block>>>(image, out);
    // iter 2: d_out -> scratch
    pm_iter_kernel<<<grid, block>>>(out, g_scratch);
    // iter 3: scratch -> d_out
    pm_iter_kernel<<<grid, block>>>(g_scratch, out);
}